// round 1
// baseline (speedup 1.0000x reference)
#include <cuda_runtime.h>
#include <cuda_bf16.h>

// Quantumnet: 10-qubit real statevector sim, warp-per-batch-element,
// statevector (1024 f32) held entirely in registers: 32 regs/lane x 32 lanes.
// Global amplitude index i (10 bits): lane = i>>5 (bits 9..5), reg = i&31 (bits 4..0).
// Reference wire w acts on bit (9-w): wires 0..4 -> lane bits 4..0 (shfl),
// wires 5..9 -> reg bits 4..0 (in-register, CNOTs there are free renames).

#define WARPS_PER_BLOCK 8
#define THREADS (WARPS_PER_BLOCK * 32)

__device__ __forceinline__ float wsum(float x) {
#pragma unroll
    for (int m = 16; m; m >>= 1) x += __shfl_xor_sync(0xffffffffu, x, m);
    return x;
}

// RY on register bit P (wire 9-? ... wire w=9-?; P = 9-w for w in 5..9)
template <int P>
__device__ __forceinline__ void ry_reg(float* v, float c, float s) {
#pragma unroll
    for (int r = 0; r < 32; r++) {
        if (!(r & (1 << P))) {
            const int r1 = r | (1 << P);
            float a = v[r], b = v[r1];
            v[r]  = c * a - s * b;
            v[r1] = s * a + c * b;
        }
    }
}

// RY on lane bit Q (wire w = 4-Q)
template <int Q>
__device__ __forceinline__ void ry_lane(float* v, float c, float s, int lane) {
    const float ss = ((lane >> Q) & 1) ? s : -s;
#pragma unroll
    for (int r = 0; r < 32; r++) {
        float p = __shfl_xor_sync(0xffffffffu, v[r], 1 << Q);
        v[r] = fmaf(c, v[r], ss * p);
    }
}

// CNOT, control lane bit QC, target lane bit QT (= QC-1)
template <int QC, int QT>
__device__ __forceinline__ void cnot_ll(float* v, int lane) {
    const bool ct = (lane >> QC) & 1;
#pragma unroll
    for (int r = 0; r < 32; r++) {
        float p = __shfl_xor_sync(0xffffffffu, v[r], 1 << QT);
        v[r] = ct ? p : v[r];
    }
}

// CNOT, control = lane bit 0 (wire 4), target = reg bit 4 (wire 5)
__device__ __forceinline__ void cnot_lr(float* v, int lane) {
    const bool ct = lane & 1;
#pragma unroll
    for (int r = 0; r < 16; r++) {
        float a = v[r], b = v[r | 16];
        v[r]      = ct ? b : a;
        v[r | 16] = ct ? a : b;
    }
}

// CNOT entirely in register bits: pure permutation -> register renaming, ~free
template <int PC, int PT>
__device__ __forceinline__ void cnot_rr(float* v) {
#pragma unroll
    for (int r = 0; r < 32; r++) {
        if ((r & (1 << PC)) && !(r & (1 << PT))) {
            const int r1 = r ^ (1 << PT);
            float t = v[r]; v[r] = v[r1]; v[r1] = t;
        }
    }
}

__global__ __launch_bounds__(THREADS)
void qnet_kernel(const float* __restrict__ x,      // [B,512]
                 const float* __restrict__ Wred,   // [10,512]
                 const float* __restrict__ bred,   // [10]
                 const float* __restrict__ qp,     // [150]
                 const float* __restrict__ Wpost,  // [2,10]
                 const float* __restrict__ bpost,  // [2]
                 float* __restrict__ out,          // [B,2]
                 int B) {
    __shared__ float sW[10 * 512];
    __shared__ float scs[6][10], ssn[6][10];
    __shared__ float sbred[10], sWp[2][10], sbp[2];

    const int tid = threadIdx.x;
    for (int i = tid; i < 10 * 512; i += THREADS) sW[i] = Wred[i];
    if (tid < 60) {
        int k = tid / 10, w = tid % 10;
        float s, c;
        sincosf(qp[(k + 1) * 10 + w] * 0.5f, &s, &c);
        scs[k][w] = c; ssn[k][w] = s;
    }
    if (tid >= 64 && tid < 74)  sbred[tid - 64] = bred[tid - 64];
    if (tid >= 96 && tid < 116) sWp[(tid - 96) / 10][(tid - 96) % 10] = Wpost[tid - 96];
    if (tid >= 128 && tid < 130) sbp[tid - 128] = bpost[tid - 128];
    __syncthreads();

    const int lane = tid & 31;
    const int b = blockIdx.x * WARPS_PER_BLOCK + (tid >> 5);
    if (b >= B) return;

    // ---- front layer: pre = x[b] @ Wred^T + bred; th = tanh(pre)*pi/2 ----
    const float* xr = x + (size_t)b * 512;
    float acc[10];
#pragma unroll
    for (int w = 0; w < 10; w++) acc[w] = 0.0f;
#pragma unroll
    for (int j = 0; j < 16; j++) {
        float xv = xr[lane + 32 * j];
#pragma unroll
        for (int w = 0; w < 10; w++)
            acc[w] = fmaf(xv, sW[w * 512 + lane + 32 * j], acc[w]);
    }
    float th[10];
#pragma unroll
    for (int w = 0; w < 10; w++) {
        float pre = wsum(acc[w]) + sbred[w];
        th[w] = tanhf(pre) * 1.5707963267948966f;
    }

    // ---- statevector: after H on all wires, uniform amplitude 1/32 ----
    float v[32];
#pragma unroll
    for (int r = 0; r < 32; r++) v[r] = 0.03125f;

    // ---- data RY layer ----
    {
        float s, c;
        sincosf(th[0] * 0.5f, &s, &c); ry_lane<4>(v, c, s, lane);
        sincosf(th[1] * 0.5f, &s, &c); ry_lane<3>(v, c, s, lane);
        sincosf(th[2] * 0.5f, &s, &c); ry_lane<2>(v, c, s, lane);
        sincosf(th[3] * 0.5f, &s, &c); ry_lane<1>(v, c, s, lane);
        sincosf(th[4] * 0.5f, &s, &c); ry_lane<0>(v, c, s, lane);
        sincosf(th[5] * 0.5f, &s, &c); ry_reg<4>(v, c, s);
        sincosf(th[6] * 0.5f, &s, &c); ry_reg<3>(v, c, s);
        sincosf(th[7] * 0.5f, &s, &c); ry_reg<2>(v, c, s);
        sincosf(th[8] * 0.5f, &s, &c); ry_reg<1>(v, c, s);
        sincosf(th[9] * 0.5f, &s, &c); ry_reg<0>(v, c, s);
    }

    // ---- 6 entangling layers (keep as a real loop: I-cache) ----
#pragma unroll 1
    for (int k = 0; k < 6; k++) {
        // even pass: ctrl wires 0,2,4,6,8 (disjoint, any order)
        cnot_ll<4, 3>(v, lane);     // ctrl 0
        cnot_ll<2, 1>(v, lane);     // ctrl 2
        cnot_lr(v, lane);           // ctrl 4
        cnot_rr<3, 2>(v);           // ctrl 6 (free)
        cnot_rr<1, 0>(v);           // ctrl 8 (free)
        // odd pass: ctrl wires 1,3,5,7
        cnot_ll<3, 2>(v, lane);     // ctrl 1
        cnot_ll<1, 0>(v, lane);     // ctrl 3
        cnot_rr<4, 3>(v);           // ctrl 5 (free)
        cnot_rr<2, 1>(v);           // ctrl 7 (free)
        // fixed RY layer (angles in shared, batch-independent)
        ry_lane<4>(v, scs[k][0], ssn[k][0], lane);
        ry_lane<3>(v, scs[k][1], ssn[k][1], lane);
        ry_lane<2>(v, scs[k][2], ssn[k][2], lane);
        ry_lane<1>(v, scs[k][3], ssn[k][3], lane);
        ry_lane<0>(v, scs[k][4], ssn[k][4], lane);
        ry_reg<4>(v, scs[k][5], ssn[k][5]);
        ry_reg<3>(v, scs[k][6], ssn[k][6]);
        ry_reg<2>(v, scs[k][7], ssn[k][7]);
        ry_reg<1>(v, scs[k][8], ssn[k][8]);
        ry_reg<0>(v, scs[k][9], ssn[k][9]);
    }

    // ---- <Z_w> and output projection, fused ----
    float S = 0.f, p4 = 0.f, p3 = 0.f, p2 = 0.f, p1 = 0.f, p0 = 0.f;
#pragma unroll
    for (int r = 0; r < 32; r++) {
        float sq = v[r] * v[r];
        S  += sq;
        p4 += (r & 16) ? -sq : sq;
        p3 += (r & 8)  ? -sq : sq;
        p2 += (r & 4)  ? -sq : sq;
        p1 += (r & 2)  ? -sq : sq;
        p0 += (r & 1)  ? -sq : sq;
    }
    float t[10];
    t[0] = (lane & 16) ? -S : S;
    t[1] = (lane & 8)  ? -S : S;
    t[2] = (lane & 4)  ? -S : S;
    t[3] = (lane & 2)  ? -S : S;
    t[4] = (lane & 1)  ? -S : S;
    t[5] = p4; t[6] = p3; t[7] = p2; t[8] = p1; t[9] = p0;

    float y0 = 0.f, y1 = 0.f;
#pragma unroll
    for (int w = 0; w < 10; w++) {
        y0 = fmaf(sWp[0][w], t[w], y0);
        y1 = fmaf(sWp[1][w], t[w], y1);
    }
    y0 = wsum(y0);
    y1 = wsum(y1);
    if (lane == 0) {
        out[2 * (size_t)b + 0] = y0 + sbp[0];
        out[2 * (size_t)b + 1] = y1 + sbp[1];
    }
}

extern "C" void kernel_launch(void* const* d_in, const int* in_sizes, int n_in,
                              void* d_out, int out_size) {
    const float* x     = (const float*)d_in[0];
    const float* Wred  = (const float*)d_in[1];
    const float* bred  = (const float*)d_in[2];
    const float* qp    = (const float*)d_in[3];
    const float* Wpost = (const float*)d_in[4];
    const float* bpost = (const float*)d_in[5];
    float* out = (float*)d_out;

    int B = in_sizes[0] / 512;
    int blocks = (B + WARPS_PER_BLOCK - 1) / WARPS_PER_BLOCK;
    qnet_kernel<<<blocks, THREADS>>>(x, Wred, bred, qp, Wpost, bpost, out, B);
}

// round 2
// speedup vs baseline: 1.3787x; 1.3787x over previous
#include <cuda_runtime.h>
#include <cuda_bf16.h>

// Quantumnet, warp-per-batch-element, statevector (1024 f32) in registers as
// 16 x f32x2 packs per lane (32 regs/lane x 32 lanes).
//
// Bit layout of amplitude index (wire w <-> one bit):
//   lane bits L4..L0  = wires 0,2,4,6,8   (even wires)
//   pack index P3..P0 = wires 1,3,5,7     (odd wires)
//   pack slot (lo/hi) = wire 9
// CNOT(even->odd): ctrl lane bit, tgt pack/slot bit -> pure SELs, no shfl.
// CNOT(odd->even): ctrl pack bit, tgt lane bit -> fused with following RY,
//                  exactly one 64-bit shfl per pack.
// All RY arithmetic in packed f32x2 (fma.rn.f32x2).

#define WARPS_PER_BLOCK 8
#define THREADS (WARPS_PER_BLOCK * 32)
typedef unsigned long long u64;

__device__ __forceinline__ u64 pk2(float lo, float hi) {
    u64 r; asm("mov.b64 %0,{%1,%2};" : "=l"(r) : "f"(lo), "f"(hi)); return r;
}
__device__ __forceinline__ void upk2(u64 x, float& lo, float& hi) {
    asm("mov.b64 {%0,%1},%2;" : "=f"(lo), "=f"(hi) : "l"(x));
}
__device__ __forceinline__ u64 fma2(u64 a, u64 b, u64 c) {
    u64 d; asm("fma.rn.f32x2 %0,%1,%2,%3;" : "=l"(d) : "l"(a), "l"(b), "l"(c)); return d;
}
__device__ __forceinline__ u64 mul2(u64 a, u64 b) {
    u64 d; asm("mul.rn.f32x2 %0,%1,%2;" : "=l"(d) : "l"(a), "l"(b)); return d;
}
__device__ __forceinline__ u64 add2(u64 a, u64 b) {
    u64 d; asm("add.rn.f32x2 %0,%1,%2;" : "=l"(d) : "l"(a), "l"(b)); return d;
}
__device__ __forceinline__ u64 shfl64(u64 x, int m) {
    return __shfl_xor_sync(0xffffffffu, x, m);
}
__device__ __forceinline__ float tanh_apx(float x) {
    float y; asm("tanh.approx.f32 %0,%1;" : "=f"(y) : "f"(x)); return y;
}
__device__ __forceinline__ u64 wsum2(u64 x) {
#pragma unroll
    for (int m = 16; m; m >>= 1) x = add2(x, shfl64(x, m));
    return x;
}

// RY on lane bit Q (wires 0,2,4,6,8)
template <int Q>
__device__ __forceinline__ void ry_lane(u64* v, u64 c2, u64 s2, u64 ns2, int lane) {
    const u64 ss2 = ((lane >> Q) & 1) ? s2 : ns2;
#pragma unroll
    for (int r = 0; r < 16; r++) {
        u64 p = shfl64(v[r], 1 << Q);
        v[r] = fma2(c2, v[r], mul2(ss2, p));
    }
}

// Fused CNOT(ctrl = pack bit CMASK, tgt = lane bit Q) + RY(tgt wire)
template <int Q, int CMASK>
__device__ __forceinline__ void cnot_ry(u64* v, u64 c2, u64 s2, u64 ns2, int lane) {
    const u64 ss2 = ((lane >> Q) & 1) ? s2 : ns2;
#pragma unroll
    for (int r = 0; r < 16; r++) {
        u64 old = v[r];
        u64 p = shfl64(old, 1 << Q);
        if (r & CMASK) v[r] = fma2(c2, p, mul2(ss2, old));   // post-CNOT amp = p, partner = old
        else           v[r] = fma2(c2, old, mul2(ss2, p));
    }
}

// RY on pack-index bit PM (wires 1,3,5,7): pure packed register math
template <int PM>
__device__ __forceinline__ void ry_pack(u64* v, u64 c2, u64 s2, u64 ns2) {
#pragma unroll
    for (int r = 0; r < 16; r++) {
        if (!(r & PM)) {
            const int r1 = r | PM;
            u64 X = v[r], Y = v[r1];
            v[r]  = fma2(c2, X, mul2(ns2, Y));
            v[r1] = fma2(c2, Y, mul2(s2, X));
        }
    }
}

// RY on the pack slot bit (wire 9): scalar within each pack
__device__ __forceinline__ void ry_slot(u64* v, float c, float s) {
#pragma unroll
    for (int r = 0; r < 16; r++) {
        float lo, hi; upk2(v[r], lo, hi);
        float nlo = fmaf(c, lo, -(s * hi));
        float nhi = fmaf(c, hi, s * lo);
        v[r] = pk2(nlo, nhi);
    }
}

// CNOT ctrl = lane bit QC, tgt = pack bit PM: predicated pack swaps, no shfl
template <int QC, int PM>
__device__ __forceinline__ void cnot_lp(u64* v, int lane) {
    const bool ct = (lane >> QC) & 1;
#pragma unroll
    for (int r = 0; r < 16; r++) {
        if (!(r & PM)) {
            const int r1 = r | PM;
            u64 a = v[r], b = v[r1];
            v[r]  = ct ? b : a;
            v[r1] = ct ? a : b;
        }
    }
}

// CNOT ctrl = lane bit 0 (wire 8), tgt = slot bit (wire 9)
__device__ __forceinline__ void cnot_ls(u64* v, int lane) {
    const bool ct = lane & 1;
#pragma unroll
    for (int r = 0; r < 16; r++) {
        float lo, hi; upk2(v[r], lo, hi);
        float nlo = ct ? hi : lo;
        float nhi = ct ? lo : hi;
        v[r] = pk2(nlo, nhi);
    }
}

__global__ __launch_bounds__(THREADS)
void qnet_kernel(const float* __restrict__ x,      // [B,512]
                 const float* __restrict__ Wred,   // [10,512]
                 const float* __restrict__ bred,   // [10]
                 const float* __restrict__ qp,     // [150]
                 const float* __restrict__ Wpost,  // [2,10]
                 const float* __restrict__ bpost,  // [2]
                 float* __restrict__ out,          // [B,2]
                 int B) {
    __shared__ u64 sW2[5 * 512];              // packed (Wred[2q], Wred[2q+1]) per column
    __shared__ u64 scs2[60], ssn2[60], snn2[60];   // (c,c),(s,s),(-s,-s) per fixed RY
    __shared__ float sbred[10], sWp[20], sbp[2];

    const int tid = threadIdx.x;
    for (int i = tid; i < 5 * 512; i += THREADS) {
        int q = i >> 9, col = i & 511;
        sW2[i] = pk2(Wred[(2 * q) * 512 + col], Wred[(2 * q + 1) * 512 + col]);
    }
    if (tid < 60) {
        int k = tid / 10, w = tid % 10;
        float s, c;
        sincosf(qp[(k + 1) * 10 + w] * 0.5f, &s, &c);
        scs2[tid] = pk2(c, c); ssn2[tid] = pk2(s, s); snn2[tid] = pk2(-s, -s);
    }
    if (tid >= 64 && tid < 74)   sbred[tid - 64] = bred[tid - 64];
    if (tid >= 96 && tid < 116)  sWp[tid - 96] = Wpost[tid - 96];
    if (tid >= 128 && tid < 130) sbp[tid - 128] = bpost[tid - 128];
    __syncthreads();

    const int lane = tid & 31;
    const int b = blockIdx.x * WARPS_PER_BLOCK + (tid >> 5);
    if (b >= B) return;

    // ---- front layer: pre = x[b] @ Wred^T + bred; th = tanh(pre)*pi/2 ----
    const float* xr = x + (size_t)b * 512;
    u64 acc2[5];
#pragma unroll
    for (int q = 0; q < 5; q++) acc2[q] = 0ull;
#pragma unroll
    for (int j = 0; j < 16; j++) {
        float xv = xr[lane + 32 * j];
        u64 xv2 = pk2(xv, xv);
#pragma unroll
        for (int q = 0; q < 5; q++)
            acc2[q] = fma2(xv2, sW2[q * 512 + lane + 32 * j], acc2[q]);
    }
    float th[10];
#pragma unroll
    for (int q = 0; q < 5; q++) {
        u64 r2 = wsum2(acc2[q]);
        float p0, p1; upk2(r2, p0, p1);
        th[2 * q]     = tanh_apx(p0 + sbred[2 * q]) * 1.5707963267948966f;
        th[2 * q + 1] = tanh_apx(p1 + sbred[2 * q + 1]) * 1.5707963267948966f;
    }

    // ---- product state after H-layer + data RY layer ----
    // per-wire: (1/sqrt2)(1,1) -> ((c-s)/sqrt2, (c+s)/sqrt2)
    float gl[5][2];   // lane wires 0,2,4,6,8 -> L4..L0
    float gp[4][2];   // pack wires 1,3,5,7   -> P3..P0
    float g9[2];
#pragma unroll
    for (int q = 0; q < 5; q++) {
        float s, c; __sincosf(th[2 * q] * 0.5f, &s, &c);
        gl[q][0] = (c - s) * 0.7071067811865476f;
        gl[q][1] = (c + s) * 0.7071067811865476f;
    }
#pragma unroll
    for (int q = 0; q < 4; q++) {
        float s, c; __sincosf(th[2 * q + 1] * 0.5f, &s, &c);
        gp[q][0] = (c - s) * 0.7071067811865476f;
        gp[q][1] = (c + s) * 0.7071067811865476f;
    }
    {
        float s, c; __sincosf(th[9] * 0.5f, &s, &c);
        g9[0] = (c - s) * 0.7071067811865476f;
        g9[1] = (c + s) * 0.7071067811865476f;
    }
    float F = ((lane & 16) ? gl[0][1] : gl[0][0]);
    F *= ((lane & 8) ? gl[1][1] : gl[1][0]);
    F *= ((lane & 4) ? gl[2][1] : gl[2][0]);
    F *= ((lane & 2) ? gl[3][1] : gl[3][0]);
    F *= ((lane & 1) ? gl[4][1] : gl[4][0]);
    float hiP[4], loP[4];
#pragma unroll
    for (int i = 0; i < 4; i++) {
        hiP[i] = gp[0][(i >> 1) & 1] * gp[1][i & 1];   // wires 1,3
        loP[i] = gp[2][(i >> 1) & 1] * gp[3][i & 1];   // wires 5,7
    }
    u64 G9F = pk2(F * g9[0], F * g9[1]);
    u64 v[16];
#pragma unroll
    for (int r = 0; r < 16; r++) {
        float m = hiP[r >> 2] * loP[r & 3];
        v[r] = mul2(pk2(m, m), G9F);
    }

    // ---- 6 entangling layers ----
#pragma unroll 1
    for (int k = 0; k < 6; k++) {
        const u64* C = scs2 + k * 10;
        const u64* S = ssn2 + k * 10;
        const u64* N = snn2 + k * 10;
        // even CNOTs (ctrl wires 0,2,4,6,8): no shuffles
        cnot_lp<4, 8>(v, lane);   // (0->1)
        cnot_lp<3, 4>(v, lane);   // (2->3)
        cnot_lp<2, 2>(v, lane);   // (4->5)
        cnot_lp<1, 1>(v, lane);   // (6->7)
        cnot_ls(v, lane);         // (8->9)
        // odd CNOTs fused with RY on their (even-wire) target
        cnot_ry<3, 8>(v, C[2], S[2], N[2], lane);  // (1->2) + RY w2
        cnot_ry<2, 4>(v, C[4], S[4], N[4], lane);  // (3->4) + RY w4
        cnot_ry<1, 2>(v, C[6], S[6], N[6], lane);  // (5->6) + RY w6
        cnot_ry<0, 1>(v, C[8], S[8], N[8], lane);  // (7->8) + RY w8
        // remaining RYs
        ry_lane<4>(v, C[0], S[0], N[0], lane);     // RY w0
        ry_pack<8>(v, C[1], S[1], N[1]);           // RY w1
        ry_pack<4>(v, C[3], S[3], N[3]);           // RY w3
        ry_pack<2>(v, C[5], S[5], N[5]);           // RY w5
        ry_pack<1>(v, C[7], S[7], N[7]);           // RY w7
        { float c, s, d;
          upk2(C[9], c, d); upk2(S[9], s, d);
          ry_slot(v, c, s); }                      // RY w9
    }

    // ---- <Z_w> + output projection, fused ----
    const u64 P1 = pk2(1.0f, 1.0f), M1 = pk2(-1.0f, -1.0f);
    u64 S2 = 0ull, A8 = 0ull, A4 = 0ull, A2 = 0ull, A1 = 0ull;
#pragma unroll
    for (int r = 0; r < 16; r++) {
        u64 sq = mul2(v[r], v[r]);
        S2 = add2(S2, sq);
        A8 = fma2((r & 8) ? M1 : P1, sq, A8);
        A4 = fma2((r & 4) ? M1 : P1, sq, A4);
        A2 = fma2((r & 2) ? M1 : P1, sq, A2);
        A1 = fma2((r & 1) ? M1 : P1, sq, A1);
    }
    float sl, sh; upk2(S2, sl, sh);
    float Sv = sl + sh;
    float t9 = sl - sh;                       // wire 9
    float l8, h8; upk2(A8, l8, h8); float t1 = l8 + h8;   // wire 1
    float l4, h4; upk2(A4, l4, h4); float t3 = l4 + h4;   // wire 3
    float l2, h2; upk2(A2, l2, h2); float t5 = l2 + h2;   // wire 5
    float l1, h1; upk2(A1, l1, h1); float t7 = l1 + h1;   // wire 7
    float t0 = (lane & 16) ? -Sv : Sv;        // wire 0
    float t2 = (lane & 8)  ? -Sv : Sv;        // wire 2
    float t4 = (lane & 4)  ? -Sv : Sv;        // wire 4
    float t6 = (lane & 2)  ? -Sv : Sv;        // wire 6
    float t8 = (lane & 1)  ? -Sv : Sv;        // wire 8

    float y0 = sWp[0] * t0 + sWp[1] * t1 + sWp[2] * t2 + sWp[3] * t3 + sWp[4] * t4
             + sWp[5] * t5 + sWp[6] * t6 + sWp[7] * t7 + sWp[8] * t8 + sWp[9] * t9;
    float y1 = sWp[10] * t0 + sWp[11] * t1 + sWp[12] * t2 + sWp[13] * t3 + sWp[14] * t4
             + sWp[15] * t5 + sWp[16] * t6 + sWp[17] * t7 + sWp[18] * t8 + sWp[19] * t9;
    u64 y2 = wsum2(pk2(y0, y1));
    if (lane == 0) {
        float r0, r1; upk2(y2, r0, r1);
        out[2 * (size_t)b + 0] = r0 + sbp[0];
        out[2 * (size_t)b + 1] = r1 + sbp[1];
    }
}

extern "C" void kernel_launch(void* const* d_in, const int* in_sizes, int n_in,
                              void* d_out, int out_size) {
    const float* x     = (const float*)d_in[0];
    const float* Wred  = (const float*)d_in[1];
    const float* bred  = (const float*)d_in[2];
    const float* qp    = (const float*)d_in[3];
    const float* Wpost = (const float*)d_in[4];
    const float* bpost = (const float*)d_in[5];
    float* out = (float*)d_out;

    int B = in_sizes[0] / 512;
    int blocks = (B + WARPS_PER_BLOCK - 1) / WARPS_PER_BLOCK;
    qnet_kernel<<<blocks, THREADS>>>(x, Wred, bred, qp, Wpost, bpost, out, B);
}

// round 3
// speedup vs baseline: 1.5793x; 1.1455x over previous
#include <cuda_runtime.h>
#include <cuda_bf16.h>

// Quantumnet, warp-per-batch-element, statevector (1024 f32) in registers as
// 16 x f32x2 packs per lane. Wire->bit map:
//   lane bits L4..L0  = wires 0,2,4,6,8 ; pack bits P3..P0 = wires 1,3,5,7 ;
//   pack slot (lo/hi) = wire 9.
// RYs use tan-half-angle with deferred cosine: out = a +- t*b, and the global
// factor F = prod(cos) over all 60 fixed rotations is folded into the initial
// product state (batch-independent). One fma2 per packed update.

#define WARPS_PER_BLOCK 8
#define THREADS (WARPS_PER_BLOCK * 32)
typedef unsigned long long u64;

__device__ __forceinline__ u64 pk2(float lo, float hi) {
    u64 r; asm("mov.b64 %0,{%1,%2};" : "=l"(r) : "f"(lo), "f"(hi)); return r;
}
__device__ __forceinline__ void upk2(u64 x, float& lo, float& hi) {
    asm("mov.b64 {%0,%1},%2;" : "=f"(lo), "=f"(hi) : "l"(x));
}
__device__ __forceinline__ u64 fma2(u64 a, u64 b, u64 c) {
    u64 d; asm("fma.rn.f32x2 %0,%1,%2,%3;" : "=l"(d) : "l"(a), "l"(b), "l"(c)); return d;
}
__device__ __forceinline__ u64 mul2(u64 a, u64 b) {
    u64 d; asm("mul.rn.f32x2 %0,%1,%2;" : "=l"(d) : "l"(a), "l"(b)); return d;
}
__device__ __forceinline__ u64 add2(u64 a, u64 b) {
    u64 d; asm("add.rn.f32x2 %0,%1,%2;" : "=l"(d) : "l"(a), "l"(b)); return d;
}
__device__ __forceinline__ u64 shfl64(u64 x, int m) {
    return __shfl_xor_sync(0xffffffffu, x, m);
}
__device__ __forceinline__ float tanh_apx(float x) {
    float y; asm("tanh.approx.f32 %0,%1;" : "=f"(y) : "f"(x)); return y;
}
__device__ __forceinline__ u64 wsum2(u64 x) {
#pragma unroll
    for (int m = 16; m; m >>= 1) x = add2(x, shfl64(x, m));
    return x;
}

// RY on lane bit Q: out = v + t_s * partner, t_s = (+t if lane bit set else -t)
template <int Q>
__device__ __forceinline__ void ry_lane(u64* v, u64 ts, int /*lane*/) {
#pragma unroll
    for (int r = 0; r < 16; r++) {
        u64 p = shfl64(v[r], 1 << Q);
        v[r] = fma2(ts, p, v[r]);
    }
}

// Fused CNOT(ctrl = pack bit CMASK, tgt = lane bit Q) + RY(tgt wire), tan form
template <int Q, int CMASK>
__device__ __forceinline__ void cnot_ry(u64* v, u64 ts) {
#pragma unroll
    for (int r = 0; r < 16; r++) {
        u64 old = v[r];
        u64 p = shfl64(old, 1 << Q);
        // post-CNOT own amp X and partner P; out = X + t_s * P
        if (r & CMASK) v[r] = fma2(ts, old, p);
        else           v[r] = fma2(ts, p, old);
    }
}

// RY on pack bit PM: X' = X - tY ; Y' = Y + tX
template <int PM>
__device__ __forceinline__ void ry_pack(u64* v, u64 tp, u64 tn) {
#pragma unroll
    for (int r = 0; r < 16; r++) {
        if (!(r & PM)) {
            const int r1 = r | PM;
            u64 X = v[r], Y = v[r1];
            v[r]  = fma2(tn, Y, X);
            v[r1] = fma2(tp, X, Y);
        }
    }
}

// RY on slot bit (wire 9): lo' = lo - t*hi ; hi' = hi + t*lo
__device__ __forceinline__ void ry_slot(u64* v, float t) {
#pragma unroll
    for (int r = 0; r < 16; r++) {
        float lo, hi; upk2(v[r], lo, hi);
        float nlo = fmaf(-t, hi, lo);
        float nhi = fmaf(t, lo, hi);
        v[r] = pk2(nlo, nhi);
    }
}

// CNOT ctrl = lane bit QC, tgt = pack bit PM: predicated pack swaps
template <int QC, int PM>
__device__ __forceinline__ void cnot_lp(u64* v, int lane) {
    const bool ct = (lane >> QC) & 1;
#pragma unroll
    for (int r = 0; r < 16; r++) {
        if (!(r & PM)) {
            const int r1 = r | PM;
            u64 a = v[r], b = v[r1];
            v[r]  = ct ? b : a;
            v[r1] = ct ? a : b;
        }
    }
}

// CNOT ctrl = lane bit 0 (wire 8), tgt = slot (wire 9)
__device__ __forceinline__ void cnot_ls(u64* v, int lane) {
    const bool ct = lane & 1;
#pragma unroll
    for (int r = 0; r < 16; r++) {
        float lo, hi; upk2(v[r], lo, hi);
        float nlo = ct ? hi : lo;
        float nhi = ct ? lo : hi;
        v[r] = pk2(nlo, nhi);
    }
}

__global__ __launch_bounds__(THREADS)
void qnet_kernel(const float* __restrict__ x,      // [B,512]
                 const float* __restrict__ Wred,   // [10,512]
                 const float* __restrict__ bred,   // [10]
                 const float* __restrict__ qp,     // [150]
                 const float* __restrict__ Wpost,  // [2,10]
                 const float* __restrict__ bpost,  // [2]
                 float* __restrict__ out,          // [B,2]
                 int B) {
    __shared__ u64 sW2[5 * 512];          // packed (Wred[2q], Wred[2q+1])
    __shared__ u64 stp[60], stn[60];      // (t,t), (-t,-t) per fixed RY
    __shared__ float scc[60];             // cosines for F product
    __shared__ float sbred[10], sWp[20], sbp[2], sF[1];

    const int tid = threadIdx.x;
    for (int i = tid; i < 5 * 512; i += THREADS) {
        int q = i >> 9, col = i & 511;
        sW2[i] = pk2(Wred[(2 * q) * 512 + col], Wred[(2 * q + 1) * 512 + col]);
    }
    if (tid < 60) {
        int k = tid / 10, w = tid % 10;
        float s, c;
        sincosf(qp[(k + 1) * 10 + w] * 0.5f, &s, &c);
        float t = s / c;
        stp[tid] = pk2(t, t); stn[tid] = pk2(-t, -t); scc[tid] = c;
    }
    if (tid >= 64 && tid < 74)   sbred[tid - 64] = bred[tid - 64];
    if (tid >= 96 && tid < 116)  sWp[tid - 96] = Wpost[tid - 96];
    if (tid >= 128 && tid < 130) sbp[tid - 128] = bpost[tid - 128];
    __syncthreads();
    if (tid == 0) {
        float f = 1.0f;
#pragma unroll
        for (int i = 0; i < 60; i++) f *= scc[i];
        sF[0] = f;
    }
    __syncthreads();

    const int lane = tid & 31;
    const int b = blockIdx.x * WARPS_PER_BLOCK + (tid >> 5);
    if (b >= B) return;

    // ---- front layer: pre = x[b] @ Wred^T + bred; th = tanh(pre)*pi/2 ----
    const float* xr = x + (size_t)b * 512;
    u64 acc2[5];
#pragma unroll
    for (int q = 0; q < 5; q++) acc2[q] = 0ull;
#pragma unroll
    for (int j = 0; j < 16; j++) {
        float xv = xr[lane + 32 * j];
        u64 xv2 = pk2(xv, xv);
#pragma unroll
        for (int q = 0; q < 5; q++)
            acc2[q] = fma2(xv2, sW2[q * 512 + lane + 32 * j], acc2[q]);
    }
    float th[10];
#pragma unroll
    for (int q = 0; q < 5; q++) {
        u64 r2 = wsum2(acc2[q]);
        float p0, p1; upk2(r2, p0, p1);
        th[2 * q]     = tanh_apx(p0 + sbred[2 * q]) * 1.5707963267948966f;
        th[2 * q + 1] = tanh_apx(p1 + sbred[2 * q + 1]) * 1.5707963267948966f;
    }

    // ---- product state: H-layer + data RY layer (exact), scaled by F ----
    float gl[5][2], gp[4][2], g9[2];
#pragma unroll
    for (int q = 0; q < 5; q++) {
        float s, c; __sincosf(th[2 * q] * 0.5f, &s, &c);
        gl[q][0] = (c - s) * 0.7071067811865476f;
        gl[q][1] = (c + s) * 0.7071067811865476f;
    }
#pragma unroll
    for (int q = 0; q < 4; q++) {
        float s, c; __sincosf(th[2 * q + 1] * 0.5f, &s, &c);
        gp[q][0] = (c - s) * 0.7071067811865476f;
        gp[q][1] = (c + s) * 0.7071067811865476f;
    }
    {
        float s, c; __sincosf(th[9] * 0.5f, &s, &c);
        g9[0] = (c - s) * 0.7071067811865476f;
        g9[1] = (c + s) * 0.7071067811865476f;
    }
    float F = sF[0] * ((lane & 16) ? gl[0][1] : gl[0][0]);
    F *= ((lane & 8) ? gl[1][1] : gl[1][0]);
    F *= ((lane & 4) ? gl[2][1] : gl[2][0]);
    F *= ((lane & 2) ? gl[3][1] : gl[3][0]);
    F *= ((lane & 1) ? gl[4][1] : gl[4][0]);
    float hiP[4], loP[4];
#pragma unroll
    for (int i = 0; i < 4; i++) {
        hiP[i] = gp[0][(i >> 1) & 1] * gp[1][i & 1];   // wires 1,3
        loP[i] = gp[2][(i >> 1) & 1] * gp[3][i & 1];   // wires 5,7
    }
    u64 G9F = pk2(F * g9[0], F * g9[1]);
    u64 v[16];
#pragma unroll
    for (int r = 0; r < 16; r++) {
        float m = hiP[r >> 2] * loP[r & 3];
        v[r] = mul2(pk2(m, m), G9F);
    }

    // ---- 6 entangling layers (tan-form RYs, deferred cosine) ----
#pragma unroll 1
    for (int k = 0; k < 6; k++) {
        const u64* TP = stp + k * 10;
        const u64* TN = stn + k * 10;
        // even CNOTs: pure register selects
        cnot_lp<4, 8>(v, lane);   // (0->1)
        cnot_lp<3, 4>(v, lane);   // (2->3)
        cnot_lp<2, 2>(v, lane);   // (4->5)
        cnot_lp<1, 1>(v, lane);   // (6->7)
        cnot_ls(v, lane);         // (8->9)
        // odd CNOTs fused with RY on their even-wire target (1 shfl + 1 fma each)
        cnot_ry<3, 8>(v, ((lane >> 3) & 1) ? TP[2] : TN[2]);  // (1->2)+RY w2
        cnot_ry<2, 4>(v, ((lane >> 2) & 1) ? TP[4] : TN[4]);  // (3->4)+RY w4
        cnot_ry<1, 2>(v, ((lane >> 1) & 1) ? TP[6] : TN[6]);  // (5->6)+RY w6
        cnot_ry<0, 1>(v, (lane & 1) ? TP[8] : TN[8]);         // (7->8)+RY w8
        // remaining RYs
        ry_lane<4>(v, ((lane >> 4) & 1) ? TP[0] : TN[0], lane);  // RY w0
        ry_pack<8>(v, TP[1], TN[1]);
        ry_pack<4>(v, TP[3], TN[3]);
        ry_pack<2>(v, TP[5], TN[5]);
        ry_pack<1>(v, TP[7], TN[7]);
        { float t, d; upk2(TP[9], t, d); ry_slot(v, t); }        // RY w9
    }

    // ---- <Z_w> + output projection, fused ----
    const u64 P1 = pk2(1.0f, 1.0f), M1 = pk2(-1.0f, -1.0f);
    u64 S2 = 0ull, A8 = 0ull, A4 = 0ull, A2 = 0ull, A1 = 0ull;
#pragma unroll
    for (int r = 0; r < 16; r++) {
        u64 sq = mul2(v[r], v[r]);
        S2 = add2(S2, sq);
        A8 = fma2((r & 8) ? M1 : P1, sq, A8);
        A4 = fma2((r & 4) ? M1 : P1, sq, A4);
        A2 = fma2((r & 2) ? M1 : P1, sq, A2);
        A1 = fma2((r & 1) ? M1 : P1, sq, A1);
    }
    float sl, sh; upk2(S2, sl, sh);
    float Sv = sl + sh;
    float t9 = sl - sh;
    float l8, h8; upk2(A8, l8, h8); float t1 = l8 + h8;
    float l4, h4; upk2(A4, l4, h4); float t3 = l4 + h4;
    float l2, h2; upk2(A2, l2, h2); float t5 = l2 + h2;
    float l1, h1; upk2(A1, l1, h1); float t7 = l1 + h1;
    float t0 = (lane & 16) ? -Sv : Sv;
    float t2 = (lane & 8)  ? -Sv : Sv;
    float t4 = (lane & 4)  ? -Sv : Sv;
    float t6 = (lane & 2)  ? -Sv : Sv;
    float t8 = (lane & 1)  ? -Sv : Sv;

    float y0 = sWp[0] * t0 + sWp[1] * t1 + sWp[2] * t2 + sWp[3] * t3 + sWp[4] * t4
             + sWp[5] * t5 + sWp[6] * t6 + sWp[7] * t7 + sWp[8] * t8 + sWp[9] * t9;
    float y1 = sWp[10] * t0 + sWp[11] * t1 + sWp[12] * t2 + sWp[13] * t3 + sWp[14] * t4
             + sWp[15] * t5 + sWp[16] * t6 + sWp[17] * t7 + sWp[18] * t8 + sWp[19] * t9;
    u64 y2 = wsum2(pk2(y0, y1));
    if (lane == 0) {
        float r0, r1; upk2(y2, r0, r1);
        out[2 * (size_t)b + 0] = r0 + sbp[0];
        out[2 * (size_t)b + 1] = r1 + sbp[1];
    }
}

extern "C" void kernel_launch(void* const* d_in, const int* in_sizes, int n_in,
                              void* d_out, int out_size) {
    const float* x     = (const float*)d_in[0];
    const float* Wred  = (const float*)d_in[1];
    const float* bred  = (const float*)d_in[2];
    const float* qp    = (const float*)d_in[3];
    const float* Wpost = (const float*)d_in[4];
    const float* bpost = (const float*)d_in[5];
    float* out = (float*)d_out;

    int B = in_sizes[0] / 512;
    int blocks = (B + WARPS_PER_BLOCK - 1) / WARPS_PER_BLOCK;
    qnet_kernel<<<blocks, THREADS>>>(x, Wred, bred, qp, Wpost, bpost, out, B);
}